// round 1
// baseline (speedup 1.0000x reference)
#include <cuda_runtime.h>
#include <math.h>
#include <stdint.h>

// Problem constants
#define BSZ   4096
#define SEQ   36
#define DM    128
#define DFFN  512
#define NLAYER 8
#define FLATD (SEQ*DM)      // 4608
#define FC1N  13824
#define MAVG  25

// ---------------- static scratch (no allocations allowed) ----------------
__device__ float g_h  [(size_t)BSZ*FLATD];
__device__ float g_q  [(size_t)BSZ*FLATD];
__device__ float g_k  [(size_t)BSZ*FLATD];
__device__ float g_v  [(size_t)BSZ*FLATD];
__device__ float g_a  [(size_t)BSZ*FLATD];
__device__ float g_s  [(size_t)BSZ*FLATD];
__device__ float g_t512[(size_t)BSZ*SEQ*DFFN];   // also reused as z2 [BSZ,4608]
__device__ float g_z1 [(size_t)BSZ*FC1N];

// ---------------- SGEMM: C = A[MxK] @ W[KxN] (+bias) (+gelu) ----------------
// M % 128 == 0 and N % 128 == 0 for all calls in this problem; only K may be ragged.
#define BM 128
#define BN 128
#define BK 16
#define PADA 17

template<int DO_GELU, int HAS_BIAS>
__global__ __launch_bounds__(256, 2)
void sgemm_kernel(const float* __restrict__ A, const float* __restrict__ W,
                  const float* __restrict__ bias, float* __restrict__ C,
                  int M, int N, int K)
{
    __shared__ float As[BM][PADA];   // [m][k]
    __shared__ float Ws[BK][BN];     // [k][n]

    const int tid = threadIdx.x;
    const int tx  = tid & 15;        // 0..15 -> column micro-tile
    const int ty  = tid >> 4;        // 0..15 -> row micro-tile
    const size_t bm = blockIdx.y;
    const size_t bn = blockIdx.x;

    const float* Ab = A + bm * BM * (size_t)K;
    const float* Wb = W + bn * BN;

    float acc[8][8];
    #pragma unroll
    for (int i = 0; i < 8; i++)
        #pragma unroll
        for (int j = 0; j < 8; j++) acc[i][j] = 0.f;

    const int ka = tid & 15;     // A-load: k within chunk
    const int ma = tid >> 4;     // A-load: base row
    const int nw = tid & 127;    // W-load: column
    const int kw = tid >> 7;     // W-load: base k row

    for (int k0 = 0; k0 < K; k0 += BK) {
        const bool kaok = (k0 + ka) < K;
        #pragma unroll
        for (int i = 0; i < 8; i++) {
            int m = ma + i * 16;
            float val = 0.f;
            if (kaok) val = Ab[(size_t)m * K + k0 + ka];
            As[m][ka] = val;
        }
        #pragma unroll
        for (int i = 0; i < 8; i++) {
            int kk = kw + i * 2;
            float val = 0.f;
            if (k0 + kk < K) val = Wb[(size_t)(k0 + kk) * N + nw];
            Ws[kk][nw] = val;
        }
        __syncthreads();

        #pragma unroll
        for (int kk = 0; kk < BK; kk++) {
            float ar[8];
            #pragma unroll
            for (int i = 0; i < 8; i++) ar[i] = As[ty * 8 + i][kk];  // broadcast
            float4 b0 = *(const float4*)&Ws[kk][tx * 8];
            float4 b1 = *(const float4*)&Ws[kk][tx * 8 + 4];
            float br[8] = {b0.x, b0.y, b0.z, b0.w, b1.x, b1.y, b1.z, b1.w};
            #pragma unroll
            for (int i = 0; i < 8; i++)
                #pragma unroll
                for (int j = 0; j < 8; j++)
                    acc[i][j] += ar[i] * br[j];
        }
        __syncthreads();
    }

    float bv[8];
    #pragma unroll
    for (int j = 0; j < 8; j++) bv[j] = 0.f;
    if (HAS_BIAS) {
        #pragma unroll
        for (int j = 0; j < 8; j++) bv[j] = bias[bn * BN + tx * 8 + j];
    }

    #pragma unroll
    for (int i = 0; i < 8; i++) {
        size_t row = bm * BM + ty * 8 + i;
        float* Cp = C + row * (size_t)N + bn * BN + tx * 8;
        float o[8];
        #pragma unroll
        for (int j = 0; j < 8; j++) {
            float vv = acc[i][j] + bv[j];
            if (DO_GELU) vv = 0.5f * vv * (1.f + erff(vv * 0.70710678118654752f));
            o[j] = vv;
        }
        *(float4*)Cp       = make_float4(o[0], o[1], o[2], o[3]);
        *(float4*)(Cp + 4) = make_float4(o[4], o[5], o[6], o[7]);
    }
}

// ---------------- AutoCorrelation (FFT == circular correlation at L=36) ----------------
// One block per batch, 128 threads = channels. corr[tau] = mean_c sum_t q[t,c]*k[(t-tau)%36,c]
__global__ __launch_bounds__(128)
void autocorr_kernel(const float* __restrict__ Q, const float* __restrict__ K,
                     const float* __restrict__ V, float* __restrict__ A)
{
    const int b = blockIdx.x;
    const int c = threadIdx.x;
    const size_t base = (size_t)b * FLATD + c;

    float qr[SEQ], kr[SEQ];
    #pragma unroll
    for (int t = 0; t < SEQ; t++) {
        qr[t] = Q[base + t * DM];
        kr[t] = K[base + t * DM];
    }

    float acc[SEQ];
    #pragma unroll
    for (int tau = 0; tau < SEQ; tau++) {
        float s = 0.f;
        #pragma unroll
        for (int t = 0; t < SEQ; t++)
            s += qr[t] * kr[(t + SEQ - tau) % SEQ];   // compile-time index
        acc[tau] = s;
    }

    const int lane = c & 31, wid = c >> 5;
    __shared__ float red[SEQ][4];
    #pragma unroll
    for (int tau = 0; tau < SEQ; tau++) {
        float s = acc[tau];
        s += __shfl_down_sync(0xffffffffu, s, 16);
        s += __shfl_down_sync(0xffffffffu, s, 8);
        s += __shfl_down_sync(0xffffffffu, s, 4);
        s += __shfl_down_sync(0xffffffffu, s, 2);
        s += __shfl_down_sync(0xffffffffu, s, 1);
        if (lane == 0) red[tau][wid] = s;
    }
    __syncthreads();

    __shared__ float corr[SEQ];
    if (c < SEQ) corr[c] = (red[c][0] + red[c][1] + red[c][2] + red[c][3]) * (1.f / 128.f);
    __syncthreads();

    __shared__ float wsm[3];
    __shared__ int   dsm[3];
    if (c == 0) {
        float tmp[SEQ];
        for (int t = 0; t < SEQ; t++) tmp[t] = corr[t];
        float wv[3]; int dv[3];
        for (int r = 0; r < 3; r++) {
            float best = tmp[0]; int bi = 0;
            for (int t = 1; t < SEQ; t++)
                if (tmp[t] > best) { best = tmp[t]; bi = t; }
            wv[r] = best; dv[r] = bi;
            tmp[bi] = -1e30f;
        }
        float m = wv[0];                            // sorted descending
        float e0 = expf(wv[0] - m), e1 = expf(wv[1] - m), e2 = expf(wv[2] - m);
        float inv = 1.f / (e0 + e1 + e2);
        wsm[0] = e0 * inv; wsm[1] = e1 * inv; wsm[2] = e2 * inv;
        dsm[0] = dv[0]; dsm[1] = dv[1]; dsm[2] = dv[2];
    }
    __syncthreads();

    const float w0 = wsm[0], w1 = wsm[1], w2 = wsm[2];
    const int   d0 = dsm[0], d1 = dsm[1], d2 = dsm[2];
    const float* vb = V + base;
    #pragma unroll
    for (int t = 0; t < SEQ; t++) {
        int j0 = t + d0; if (j0 >= SEQ) j0 -= SEQ;
        int j1 = t + d1; if (j1 >= SEQ) j1 -= SEQ;
        int j2 = t + d2; if (j2 >= SEQ) j2 -= SEQ;
        A[base + t * DM] = w0 * vb[j0 * DM] + w1 * vb[j1 * DM] + w2 * vb[j2 * DM];
    }
}

// ---------------- series_decomp with fused residual add ----------------
// out = (h+s) - movavg(h+s, 25, replicate pad 12). One block per batch, thread = channel.
__global__ __launch_bounds__(128)
void decomp_add_kernel(const float* __restrict__ hin, const float* __restrict__ sin_,
                       float* __restrict__ hout)
{
    const int b = blockIdx.x;
    const int c = threadIdx.x;
    __shared__ float p[SEQ][DM];
    const size_t base = (size_t)b * FLATD + c;
    #pragma unroll
    for (int t = 0; t < SEQ; t++)
        p[t][c] = hin[base + t * DM] + sin_[base + t * DM];
    __syncthreads();

    float run = 12.f * p[0][c];               // replicate left pad
    #pragma unroll
    for (int j = 0; j <= 12; j++) run += p[j][c];
    #pragma unroll
    for (int t = 0; t < SEQ; t++) {
        hout[base + t * DM] = p[t][c] - run * (1.f / 25.f);
        int jn = t + 13; if (jn > SEQ - 1) jn = SEQ - 1;
        int jo = t - 12; if (jo < 0) jo = 0;
        run += p[jn][c] - p[jo][c];
    }
}

// ---------------- my_Layernorm: LN over features, subtract per-sample time-mean ----------------
__global__ __launch_bounds__(128)
void ln_kernel(const float* __restrict__ hin, const float* __restrict__ lnw,
               const float* __restrict__ lnb, float* __restrict__ hout)
{
    const int b = blockIdx.x;
    const int c = threadIdx.x;
    const int lane = c & 31, wid = c >> 5;
    __shared__ float xs[SEQ][DM];
    __shared__ float r1[4], r2[4];
    const size_t base = (size_t)b * FLATD + c;
    #pragma unroll
    for (int t = 0; t < SEQ; t++) xs[t][c] = hin[base + t * DM];
    __syncthreads();

    const float gw = lnw[c], gb = lnb[c];
    for (int t = 0; t < SEQ; t++) {
        float val = xs[t][c];
        float s = val;
        s += __shfl_down_sync(0xffffffffu, s, 16);
        s += __shfl_down_sync(0xffffffffu, s, 8);
        s += __shfl_down_sync(0xffffffffu, s, 4);
        s += __shfl_down_sync(0xffffffffu, s, 2);
        s += __shfl_down_sync(0xffffffffu, s, 1);
        if (lane == 0) r1[wid] = s;
        __syncthreads();
        float mean = (r1[0] + r1[1] + r1[2] + r1[3]) * (1.f / 128.f);
        float d = val - mean;
        float sq = d * d;
        sq += __shfl_down_sync(0xffffffffu, sq, 16);
        sq += __shfl_down_sync(0xffffffffu, sq, 8);
        sq += __shfl_down_sync(0xffffffffu, sq, 4);
        sq += __shfl_down_sync(0xffffffffu, sq, 2);
        sq += __shfl_down_sync(0xffffffffu, sq, 1);
        if (lane == 0) r2[wid] = sq;
        __syncthreads();
        float var = (r2[0] + r2[1] + r2[2] + r2[3]) * (1.f / 128.f);
        xs[t][c] = d * (1.f / sqrtf(var + 1e-5f)) * gw + gb;
    }
    // column (time) mean — purely thread-local per channel
    float cm = 0.f;
    #pragma unroll
    for (int t = 0; t < SEQ; t++) cm += xs[t][c];
    cm *= (1.f / 36.f);
    #pragma unroll
    for (int t = 0; t < SEQ; t++)
        hout[base + t * DM] = xs[t][c] - cm;
}

// ---------------- fc3 [4608 -> 2] + softmax ----------------
__global__ __launch_bounds__(256)
void fc3_softmax_kernel(const float* __restrict__ z, const float* __restrict__ w,
                        const float* __restrict__ bias, float* __restrict__ out)
{
    const int b = blockIdx.x;
    const int tid = threadIdx.x;
    const int lane = tid & 31, wid = tid >> 5;
    const float* zb = z + (size_t)b * FLATD;
    float s0 = 0.f, s1 = 0.f;
    for (int i = tid; i < FLATD; i += 256) {
        float zi = zb[i];
        s0 += zi * w[2 * i];
        s1 += zi * w[2 * i + 1];
    }
    for (int off = 16; off; off >>= 1) {
        s0 += __shfl_down_sync(0xffffffffu, s0, off);
        s1 += __shfl_down_sync(0xffffffffu, s1, off);
    }
    __shared__ float r0[8], r1[8];
    if (lane == 0) { r0[wid] = s0; r1[wid] = s1; }
    __syncthreads();
    if (tid == 0) {
        float z0 = bias[0], z1v = bias[1];
        #pragma unroll
        for (int i = 0; i < 8; i++) { z0 += r0[i]; z1v += r1[i]; }
        float m = fmaxf(z0, z1v);
        float e0 = expf(z0 - m), e1 = expf(z1v - m);
        float inv = 1.f / (e0 + e1);
        out[2 * b]     = e0 * inv;
        out[2 * b + 1] = e1 * inv;
    }
}

// ---------------- launch ----------------
extern "C" void kernel_launch(void* const* d_in, const int* in_sizes, int n_in,
                              void* d_out, int out_size)
{
    const float* x        = (const float*)d_in[0];
    const float* linear_w = (const float*)d_in[1];
    const float* linear_b = (const float*)d_in[2];
    const float* Wq = (const float*)d_in[3];
    const float* bq = (const float*)d_in[4];
    const float* Wk = (const float*)d_in[5];
    const float* bk = (const float*)d_in[6];
    const float* Wv = (const float*)d_in[7];
    const float* bv = (const float*)d_in[8];
    const float* Wo = (const float*)d_in[9];
    const float* bo = (const float*)d_in[10];
    const float* conv1_w = (const float*)d_in[11];
    const float* conv2_w = (const float*)d_in[12];
    const float* ln_w = (const float*)d_in[13];
    const float* ln_b = (const float*)d_in[14];
    const float* fc1_w = (const float*)d_in[15];
    const float* fc1_b = (const float*)d_in[16];
    const float* fc2_w = (const float*)d_in[17];
    const float* fc2_b = (const float*)d_in[18];
    const float* fc3_w = (const float*)d_in[19];
    const float* fc3_b = (const float*)d_in[20];

    float *h, *q, *k, *v, *a, *s, *t512, *z1;
    cudaGetSymbolAddress((void**)&h,    g_h);
    cudaGetSymbolAddress((void**)&q,    g_q);
    cudaGetSymbolAddress((void**)&k,    g_k);
    cudaGetSymbolAddress((void**)&v,    g_v);
    cudaGetSymbolAddress((void**)&a,    g_a);
    cudaGetSymbolAddress((void**)&s,    g_s);
    cudaGetSymbolAddress((void**)&t512, g_t512);
    cudaGetSymbolAddress((void**)&z1,   g_z1);

    const int BL = BSZ * SEQ;   // 147456

    // h = x @ linear_w + linear_b  : [4096,36] @ [36,4608]
    sgemm_kernel<0,1><<<dim3(FLATD/BN, BSZ/BM), 256>>>(x, linear_w, linear_b, h, BSZ, FLATD, 36);

    for (int i = 0; i < NLAYER; i++) {
        const float* wq = Wq + (size_t)i * DM * DM;
        const float* wk = Wk + (size_t)i * DM * DM;
        const float* wv = Wv + (size_t)i * DM * DM;
        const float* wo = Wo + (size_t)i * DM * DM;
        const float* c1 = conv1_w + (size_t)i * DM * DFFN;
        const float* c2 = conv2_w + (size_t)i * DFFN * DM;

        sgemm_kernel<0,1><<<dim3(1, BL/BM), 256>>>(h, wq, bq + i*DM, q, BL, DM, DM);
        sgemm_kernel<0,1><<<dim3(1, BL/BM), 256>>>(h, wk, bk + i*DM, k, BL, DM, DM);
        sgemm_kernel<0,1><<<dim3(1, BL/BM), 256>>>(h, wv, bv + i*DM, v, BL, DM, DM);

        autocorr_kernel<<<BSZ, 128>>>(q, k, v, a);

        sgemm_kernel<0,1><<<dim3(1, BL/BM), 256>>>(a, wo, bo + i*DM, s, BL, DM, DM);
        decomp_add_kernel<<<BSZ, 128>>>(h, s, h);

        sgemm_kernel<1,0><<<dim3(DFFN/BN, BL/BM), 256>>>(h, c1, nullptr, t512, BL, DFFN, DM);
        sgemm_kernel<0,0><<<dim3(1, BL/BM), 256>>>(t512, c2, nullptr, s, BL, DM, DFFN);
        decomp_add_kernel<<<BSZ, 128>>>(h, s, h);
    }

    ln_kernel<<<BSZ, 128>>>(h, ln_w, ln_b, h);

    // fc1: [4096,4608] @ [4608,13824] + gelu
    sgemm_kernel<1,1><<<dim3(FC1N/BN, BSZ/BM), 256>>>(h, fc1_w, fc1_b, z1, BSZ, FC1N, FLATD);
    // fc2: [4096,13824] @ [13824,4608]   (output into t512 scratch, viewed as [4096,4608])
    sgemm_kernel<0,1><<<dim3(FLATD/BN, BSZ/BM), 256>>>(z1, fc2_w, fc2_b, t512, BSZ, FLATD, FC1N);
    // fc3 + softmax
    fc3_softmax_kernel<<<BSZ, 256>>>(t512, fc3_w, fc3_b, (float*)d_out);
}

// round 4
// speedup vs baseline: 1.2903x; 1.2903x over previous
#include <cuda_runtime.h>
#include <math.h>
#include <stdint.h>

// Problem constants
#define BSZ   4096
#define SEQ   36
#define DM    128
#define DFFN  512
#define NLAYER 8
#define FLATD (SEQ*DM)      // 4608
#define FC1N  13824

// ---------------- static scratch ----------------
__device__ float g_h  [(size_t)BSZ*FLATD];
__device__ float g_q  [(size_t)BSZ*FLATD];
__device__ float g_k  [(size_t)BSZ*FLATD];
__device__ float g_v  [(size_t)BSZ*FLATD];
__device__ float g_s  [(size_t)BSZ*FLATD];
__device__ float g_t512[(size_t)BSZ*SEQ*DFFN];   // also reused as z2 [BSZ,4608]
__device__ float g_z1 [(size_t)BSZ*FC1N];

// ============================================================================
// fp32 SGEMM — entire encoder (bit-stable; protects top-k delay decisions)
// ============================================================================
#define BM 128
#define BN 128
#define BK 16
#define PADA 17

template<int DO_GELU, int HAS_BIAS>
__global__ __launch_bounds__(256, 2)
void sgemm_kernel(const float* __restrict__ A, const float* __restrict__ W,
                  const float* __restrict__ bias, float* __restrict__ C,
                  int M, int N, int K)
{
    __shared__ float As[BM][PADA];
    __shared__ float Ws[BK][BN];

    const int tid = threadIdx.x;
    const int tx  = tid & 15;
    const int ty  = tid >> 4;
    const size_t bm = blockIdx.y;
    const size_t bn = blockIdx.x;

    const float* Ab = A + bm * BM * (size_t)K;
    const float* Wb = W + bn * BN;

    float acc[8][8];
    #pragma unroll
    for (int i = 0; i < 8; i++)
        #pragma unroll
        for (int j = 0; j < 8; j++) acc[i][j] = 0.f;

    const int ka = tid & 15;
    const int ma = tid >> 4;
    const int nw = tid & 127;
    const int kw = tid >> 7;

    for (int k0 = 0; k0 < K; k0 += BK) {
        const bool kaok = (k0 + ka) < K;
        #pragma unroll
        for (int i = 0; i < 8; i++) {
            int m = ma + i * 16;
            float val = 0.f;
            if (kaok) val = Ab[(size_t)m * K + k0 + ka];
            As[m][ka] = val;
        }
        #pragma unroll
        for (int i = 0; i < 8; i++) {
            int kk = kw + i * 2;
            float val = 0.f;
            if (k0 + kk < K) val = Wb[(size_t)(k0 + kk) * N + nw];
            Ws[kk][nw] = val;
        }
        __syncthreads();

        #pragma unroll
        for (int kk = 0; kk < BK; kk++) {
            float ar[8];
            #pragma unroll
            for (int i = 0; i < 8; i++) ar[i] = As[ty * 8 + i][kk];
            float4 b0 = *(const float4*)&Ws[kk][tx * 8];
            float4 b1 = *(const float4*)&Ws[kk][tx * 8 + 4];
            float br[8] = {b0.x, b0.y, b0.z, b0.w, b1.x, b1.y, b1.z, b1.w};
            #pragma unroll
            for (int i = 0; i < 8; i++)
                #pragma unroll
                for (int j = 0; j < 8; j++)
                    acc[i][j] += ar[i] * br[j];
        }
        __syncthreads();
    }

    float bv[8];
    #pragma unroll
    for (int j = 0; j < 8; j++) bv[j] = 0.f;
    if (HAS_BIAS) {
        #pragma unroll
        for (int j = 0; j < 8; j++) bv[j] = bias[bn * BN + tx * 8 + j];
    }

    #pragma unroll
    for (int i = 0; i < 8; i++) {
        size_t row = bm * BM + ty * 8 + i;
        float* Cp = C + row * (size_t)N + bn * BN + tx * 8;
        float o[8];
        #pragma unroll
        for (int j = 0; j < 8; j++) {
            float vv = acc[i][j] + bv[j];
            if (DO_GELU) vv = 0.5f * vv * (1.f + erff(vv * 0.70710678118654752f));
            o[j] = vv;
        }
        *(float4*)Cp       = make_float4(o[0], o[1], o[2], o[3]);
        *(float4*)(Cp + 4) = make_float4(o[4], o[5], o[6], o[7]);
    }
}

// ============================================================================
// 3xTF32 tensor-core GEMM (head only): effectively fp32-accurate.
// a = hi+lo (tf32 split); acc += hi*hi + hi*lo + lo*hi.
// Block 128x128, 8 warps 2(M)x4(N), warp tile 64x32, mma.m16n8k8.
// Single-buffered smem (hi+lo fits 48KB static), register prefetch.
// ============================================================================
#define TBK 16
#define ASTR 20
#define WSTR 136

__device__ __forceinline__ uint32_t f2tf(float f) {
    uint32_t u;
    asm("cvt.rna.tf32.f32 %0, %1;" : "=r"(u) : "f"(f));
    return u;
}
__device__ __forceinline__ void split_tf32(float f, uint32_t& h, uint32_t& l) {
    h = f2tf(f);
    l = f2tf(f - __uint_as_float(h));
}

#define MMA_TF32(ACC, A0, A1, A2, A3, B0, B1)                                   \
    asm volatile(                                                                \
        "mma.sync.aligned.m16n8k8.row.col.f32.tf32.tf32.f32 "                   \
        "{%0,%1,%2,%3}, {%4,%5,%6,%7}, {%8,%9}, {%0,%1,%2,%3};\n"               \
        : "+f"(ACC[0]), "+f"(ACC[1]), "+f"(ACC[2]), "+f"(ACC[3])                \
        : "r"(A0), "r"(A1), "r"(A2), "r"(A3), "r"(B0), "r"(B1))

template<int DO_GELU, int HAS_BIAS>
__global__ __launch_bounds__(256, 2)
void tgemm3_kernel(const float* __restrict__ A, const float* __restrict__ W,
                   const float* __restrict__ bias, float* __restrict__ C,
                   int M, int N, int K)
{
    __shared__ uint32_t Ash[128 * ASTR];
    __shared__ uint32_t Asl[128 * ASTR];
    __shared__ uint32_t Wsh[TBK * WSTR];
    __shared__ uint32_t Wsl[TBK * WSTR];

    const int tid  = threadIdx.x;
    const int warp = tid >> 5;
    const int lane = tid & 31;
    const int wm = warp >> 2;
    const int wn = warp & 3;
    const int g  = lane >> 2;
    const int t4 = lane & 3;

    const long bm = blockIdx.y;
    const long bn = blockIdx.x;
    const float* Ab = A + bm * 128 * (long)K;
    const float* Wb = W + bn * 128;

    const int arow = tid >> 2;
    const int acol = (tid & 3) * 4;
    const int wrow = tid >> 5;
    const int wcol = (tid & 31) * 4;

    float acc[4][4][4];
    #pragma unroll
    for (int mi = 0; mi < 4; mi++)
        #pragma unroll
        for (int ni = 0; ni < 4; ni++)
            #pragma unroll
            for (int r = 0; r < 4; r++) acc[mi][ni][r] = 0.f;

    float4 pa0, pa1, pw0, pw1;
    pa0 = *(const float4*)(Ab + (long)arow * K + acol);
    pa1 = *(const float4*)(Ab + (long)(arow + 64) * K + acol);
    pw0 = *(const float4*)(Wb + (long)wrow * N + wcol);
    pw1 = *(const float4*)(Wb + (long)(wrow + 8) * N + wcol);

    for (int k0 = 0; k0 < K; k0 += TBK) {
        // store current tile (split hi/lo)
        {
            uint4 uh, ul;
            split_tf32(pa0.x, uh.x, ul.x); split_tf32(pa0.y, uh.y, ul.y);
            split_tf32(pa0.z, uh.z, ul.z); split_tf32(pa0.w, uh.w, ul.w);
            *(uint4*)&Ash[arow * ASTR + acol] = uh;
            *(uint4*)&Asl[arow * ASTR + acol] = ul;
            split_tf32(pa1.x, uh.x, ul.x); split_tf32(pa1.y, uh.y, ul.y);
            split_tf32(pa1.z, uh.z, ul.z); split_tf32(pa1.w, uh.w, ul.w);
            *(uint4*)&Ash[(arow + 64) * ASTR + acol] = uh;
            *(uint4*)&Asl[(arow + 64) * ASTR + acol] = ul;
            split_tf32(pw0.x, uh.x, ul.x); split_tf32(pw0.y, uh.y, ul.y);
            split_tf32(pw0.z, uh.z, ul.z); split_tf32(pw0.w, uh.w, ul.w);
            *(uint4*)&Wsh[wrow * WSTR + wcol] = uh;
            *(uint4*)&Wsl[wrow * WSTR + wcol] = ul;
            split_tf32(pw1.x, uh.x, ul.x); split_tf32(pw1.y, uh.y, ul.y);
            split_tf32(pw1.z, uh.z, ul.z); split_tf32(pw1.w, uh.w, ul.w);
            *(uint4*)&Wsh[(wrow + 8) * WSTR + wcol] = uh;
            *(uint4*)&Wsl[(wrow + 8) * WSTR + wcol] = ul;
        }
        __syncthreads();

        // prefetch next tile into registers (overlaps the mma block)
        const int knext = k0 + TBK;
        const bool more = (knext < K);
        if (more) {
            pa0 = *(const float4*)(Ab + (long)arow * K + knext + acol);
            pa1 = *(const float4*)(Ab + (long)(arow + 64) * K + knext + acol);
            pw0 = *(const float4*)(Wb + (long)(knext + wrow) * N + wcol);
            pw1 = *(const float4*)(Wb + (long)(knext + wrow + 8) * N + wcol);
        }

        #pragma unroll
        for (int ks = 0; ks < 2; ks++) {
            const int kb = ks * 8;
            uint32_t afr[4][4];
            uint32_t bfr[4][2];
            // pass 1: hi * hi
            #pragma unroll
            for (int mi = 0; mi < 4; mi++) {
                const int r = wm * 64 + mi * 16 + g;
                afr[mi][0] = Ash[r * ASTR + kb + t4];
                afr[mi][1] = Ash[(r + 8) * ASTR + kb + t4];
                afr[mi][2] = Ash[r * ASTR + kb + t4 + 4];
                afr[mi][3] = Ash[(r + 8) * ASTR + kb + t4 + 4];
            }
            #pragma unroll
            for (int ni = 0; ni < 4; ni++) {
                const int cl = wn * 32 + ni * 8 + g;
                bfr[ni][0] = Wsh[(kb + t4) * WSTR + cl];
                bfr[ni][1] = Wsh[(kb + t4 + 4) * WSTR + cl];
            }
            #pragma unroll
            for (int mi = 0; mi < 4; mi++)
                #pragma unroll
                for (int ni = 0; ni < 4; ni++)
                    MMA_TF32(acc[mi][ni], afr[mi][0], afr[mi][1], afr[mi][2], afr[mi][3],
                             bfr[ni][0], bfr[ni][1]);
            // pass 2: hi * lo   (a_hi still resident, swap b -> lo)
            #pragma unroll
            for (int ni = 0; ni < 4; ni++) {
                const int cl = wn * 32 + ni * 8 + g;
                bfr[ni][0] = Wsl[(kb + t4) * WSTR + cl];
                bfr[ni][1] = Wsl[(kb + t4 + 4) * WSTR + cl];
            }
            #pragma unroll
            for (int mi = 0; mi < 4; mi++)
                #pragma unroll
                for (int ni = 0; ni < 4; ni++)
                    MMA_TF32(acc[mi][ni], afr[mi][0], afr[mi][1], afr[mi][2], afr[mi][3],
                             bfr[ni][0], bfr[ni][1]);
            // pass 3: lo * hi   (swap a -> lo, reload b_hi)
            #pragma unroll
            for (int mi = 0; mi < 4; mi++) {
                const int r = wm * 64 + mi * 16 + g;
                afr[mi][0] = Asl[r * ASTR + kb + t4];
                afr[mi][1] = Asl[(r + 8) * ASTR + kb + t4];
                afr[mi][2] = Asl[r * ASTR + kb + t4 + 4];
                afr[mi][3] = Asl[(r + 8) * ASTR + kb + t4 + 4];
            }
            #pragma unroll
            for (int ni = 0; ni < 4; ni++) {
                const int cl = wn * 32 + ni * 8 + g;
                bfr[ni][0] = Wsh[(kb + t4) * WSTR + cl];
                bfr[ni][1] = Wsh[(kb + t4 + 4) * WSTR + cl];
            }
            #pragma unroll
            for (int mi = 0; mi < 4; mi++)
                #pragma unroll
                for (int ni = 0; ni < 4; ni++)
                    MMA_TF32(acc[mi][ni], afr[mi][0], afr[mi][1], afr[mi][2], afr[mi][3],
                             bfr[ni][0], bfr[ni][1]);
        }
        __syncthreads();
    }

    // epilogue
    #pragma unroll
    for (int ni = 0; ni < 4; ni++) {
        const int col = (int)bn * 128 + wn * 32 + ni * 8 + 2 * t4;
        float b0 = 0.f, b1 = 0.f;
        if (HAS_BIAS) { b0 = bias[col]; b1 = bias[col + 1]; }
        #pragma unroll
        for (int mi = 0; mi < 4; mi++) {
            #pragma unroll
            for (int h = 0; h < 2; h++) {
                const long row = bm * 128 + wm * 64 + mi * 16 + g + h * 8;
                float v0 = acc[mi][ni][2 * h]     + b0;
                float v1 = acc[mi][ni][2 * h + 1] + b1;
                if (DO_GELU) {
                    v0 = 0.5f * v0 * (1.f + erff(v0 * 0.70710678118654752f));
                    v1 = 0.5f * v1 * (1.f + erff(v1 * 0.70710678118654752f));
                }
                *(float2*)(C + row * (long)N + col) = make_float2(v0, v1);
            }
        }
    }
}

// ============================================================================
// AutoCorrelation (exact fp32)
// ============================================================================
__global__ __launch_bounds__(128)
void autocorr_kernel(const float* __restrict__ Q, const float* __restrict__ K,
                     const float* __restrict__ V, float* __restrict__ A)
{
    const int b = blockIdx.x;
    const int c = threadIdx.x;
    const size_t base = (size_t)b * FLATD + c;

    float qr[SEQ], kr[SEQ];
    #pragma unroll
    for (int t = 0; t < SEQ; t++) {
        qr[t] = Q[base + t * DM];
        kr[t] = K[base + t * DM];
    }

    float acc[SEQ];
    #pragma unroll
    for (int tau = 0; tau < SEQ; tau++) {
        float s = 0.f;
        #pragma unroll
        for (int t = 0; t < SEQ; t++)
            s += qr[t] * kr[(t + SEQ - tau) % SEQ];
        acc[tau] = s;
    }

    const int lane = c & 31, wid = c >> 5;
    __shared__ float red[SEQ][4];
    #pragma unroll
    for (int tau = 0; tau < SEQ; tau++) {
        float s = acc[tau];
        s += __shfl_down_sync(0xffffffffu, s, 16);
        s += __shfl_down_sync(0xffffffffu, s, 8);
        s += __shfl_down_sync(0xffffffffu, s, 4);
        s += __shfl_down_sync(0xffffffffu, s, 2);
        s += __shfl_down_sync(0xffffffffu, s, 1);
        if (lane == 0) red[tau][wid] = s;
    }
    __syncthreads();

    __shared__ float corr[SEQ];
    if (c < SEQ) corr[c] = (red[c][0] + red[c][1] + red[c][2] + red[c][3]) * (1.f / 128.f);
    __syncthreads();

    __shared__ float wsm[3];
    __shared__ int   dsm[3];
    if (c == 0) {
        float tmp[SEQ];
        for (int t = 0; t < SEQ; t++) tmp[t] = corr[t];
        float wv[3]; int dv[3];
        for (int r = 0; r < 3; r++) {
            float best = tmp[0]; int bi = 0;
            for (int t = 1; t < SEQ; t++)
                if (tmp[t] > best) { best = tmp[t]; bi = t; }
            wv[r] = best; dv[r] = bi;
            tmp[bi] = -1e30f;
        }
        float m = wv[0];
        float e0 = expf(wv[0] - m), e1 = expf(wv[1] - m), e2 = expf(wv[2] - m);
        float inv = 1.f / (e0 + e1 + e2);
        wsm[0] = e0 * inv; wsm[1] = e1 * inv; wsm[2] = e2 * inv;
        dsm[0] = dv[0]; dsm[1] = dv[1]; dsm[2] = dv[2];
    }
    __syncthreads();

    const float w0 = wsm[0], w1 = wsm[1], w2 = wsm[2];
    const int   d0 = dsm[0], d1 = dsm[1], d2 = dsm[2];
    const float* vb = V + base;
    #pragma unroll
    for (int t = 0; t < SEQ; t++) {
        int j0 = t + d0; if (j0 >= SEQ) j0 -= SEQ;
        int j1 = t + d1; if (j1 >= SEQ) j1 -= SEQ;
        int j2 = t + d2; if (j2 >= SEQ) j2 -= SEQ;
        A[base + t * DM] = w0 * vb[j0 * DM] + w1 * vb[j1 * DM] + w2 * vb[j2 * DM];
    }
}

// ---------------- series_decomp with fused residual add ----------------
__global__ __launch_bounds__(128)
void decomp_add_kernel(const float* __restrict__ hin, const float* __restrict__ sin_,
                       float* __restrict__ hout)
{
    const int b = blockIdx.x;
    const int c = threadIdx.x;
    __shared__ float p[SEQ][DM];
    const size_t base = (size_t)b * FLATD + c;
    #pragma unroll
    for (int t = 0; t < SEQ; t++)
        p[t][c] = hin[base + t * DM] + sin_[base + t * DM];
    __syncthreads();

    float run = 12.f * p[0][c];
    #pragma unroll
    for (int j = 0; j <= 12; j++) run += p[j][c];
    #pragma unroll
    for (int t = 0; t < SEQ; t++) {
        hout[base + t * DM] = p[t][c] - run * (1.f / 25.f);
        int jn = t + 13; if (jn > SEQ - 1) jn = SEQ - 1;
        int jo = t - 12; if (jo < 0) jo = 0;
        run += p[jn][c] - p[jo][c];
    }
}

// ---------------- my_Layernorm ----------------
__global__ __launch_bounds__(128)
void ln_kernel(const float* __restrict__ hin, const float* __restrict__ lnw,
               const float* __restrict__ lnb, float* __restrict__ hout)
{
    const int b = blockIdx.x;
    const int c = threadIdx.x;
    const int lane = c & 31, wid = c >> 5;
    __shared__ float xs[SEQ][DM];
    __shared__ float r1[4], r2[4];
    const size_t base = (size_t)b * FLATD + c;
    #pragma unroll
    for (int t = 0; t < SEQ; t++) xs[t][c] = hin[base + t * DM];
    __syncthreads();

    const float gw = lnw[c], gb = lnb[c];
    for (int t = 0; t < SEQ; t++) {
        float val = xs[t][c];
        float s = val;
        s += __shfl_down_sync(0xffffffffu, s, 16);
        s += __shfl_down_sync(0xffffffffu, s, 8);
        s += __shfl_down_sync(0xffffffffu, s, 4);
        s += __shfl_down_sync(0xffffffffu, s, 2);
        s += __shfl_down_sync(0xffffffffu, s, 1);
        if (lane == 0) r1[wid] = s;
        __syncthreads();
        float mean = (r1[0] + r1[1] + r1[2] + r1[3]) * (1.f / 128.f);
        float d = val - mean;
        float sq = d * d;
        sq += __shfl_down_sync(0xffffffffu, sq, 16);
        sq += __shfl_down_sync(0xffffffffu, sq, 8);
        sq += __shfl_down_sync(0xffffffffu, sq, 4);
        sq += __shfl_down_sync(0xffffffffu, sq, 2);
        sq += __shfl_down_sync(0xffffffffu, sq, 1);
        if (lane == 0) r2[wid] = sq;
        __syncthreads();
        float var = (r2[0] + r2[1] + r2[2] + r2[3]) * (1.f / 128.f);
        xs[t][c] = d * (1.f / sqrtf(var + 1e-5f)) * gw + gb;
    }
    float cm = 0.f;
    #pragma unroll
    for (int t = 0; t < SEQ; t++) cm += xs[t][c];
    cm *= (1.f / 36.f);
    #pragma unroll
    for (int t = 0; t < SEQ; t++)
        hout[base + t * DM] = xs[t][c] - cm;
}

// ---------------- fc3 [4608 -> 2] + softmax ----------------
__global__ __launch_bounds__(256)
void fc3_softmax_kernel(const float* __restrict__ z, const float* __restrict__ w,
                        const float* __restrict__ bias, float* __restrict__ out)
{
    const int b = blockIdx.x;
    const int tid = threadIdx.x;
    const int lane = tid & 31, wid = tid >> 5;
    const float* zb = z + (size_t)b * FLATD;
    float s0 = 0.f, s1 = 0.f;
    for (int i = tid; i < FLATD; i += 256) {
        float zi = zb[i];
        s0 += zi * w[2 * i];
        s1 += zi * w[2 * i + 1];
    }
    for (int off = 16; off; off >>= 1) {
        s0 += __shfl_down_sync(0xffffffffu, s0, off);
        s1 += __shfl_down_sync(0xffffffffu, s1, off);
    }
    __shared__ float r0[8], r1[8];
    if (lane == 0) { r0[wid] = s0; r1[wid] = s1; }
    __syncthreads();
    if (tid == 0) {
        float z0 = bias[0], z1v = bias[1];
        #pragma unroll
        for (int i = 0; i < 8; i++) { z0 += r0[i]; z1v += r1[i]; }
        float m = fmaxf(z0, z1v);
        float e0 = expf(z0 - m), e1 = expf(z1v - m);
        float inv = 1.f / (e0 + e1);
        out[2 * b]     = e0 * inv;
        out[2 * b + 1] = e1 * inv;
    }
}

// ---------------- launch ----------------
extern "C" void kernel_launch(void* const* d_in, const int* in_sizes, int n_in,
                              void* d_out, int out_size)
{
    const float* x        = (const float*)d_in[0];
    const float* linear_w = (const float*)d_in[1];
    const float* linear_b = (const float*)d_in[2];
    const float* Wq = (const float*)d_in[3];
    const float* bq = (const float*)d_in[4];
    const float* Wk = (const float*)d_in[5];
    const float* bk = (const float*)d_in[6];
    const float* Wv = (const float*)d_in[7];
    const float* bv = (const float*)d_in[8];
    const float* Wo = (const float*)d_in[9];
    const float* bo = (const float*)d_in[10];
    const float* conv1_w = (const float*)d_in[11];
    const float* conv2_w = (const float*)d_in[12];
    const float* ln_w = (const float*)d_in[13];
    const float* ln_b = (const float*)d_in[14];
    const float* fc1_w = (const float*)d_in[15];
    const float* fc1_b = (const float*)d_in[16];
    const float* fc2_w = (const float*)d_in[17];
    const float* fc2_b = (const float*)d_in[18];
    const float* fc3_w = (const float*)d_in[19];
    const float* fc3_b = (const float*)d_in[20];

    float *h, *q, *k, *v, *s, *t512, *z1;
    cudaGetSymbolAddress((void**)&h,    g_h);
    cudaGetSymbolAddress((void**)&q,    g_q);
    cudaGetSymbolAddress((void**)&k,    g_k);
    cudaGetSymbolAddress((void**)&v,    g_v);
    cudaGetSymbolAddress((void**)&s,    g_s);
    cudaGetSymbolAddress((void**)&t512, g_t512);
    cudaGetSymbolAddress((void**)&z1,   g_z1);

    const int BL = BSZ * SEQ;   // 147456

    // ----- encoder: ALL fp32, bit-identical to round-1 passing run -----
    sgemm_kernel<0,1><<<dim3(FLATD/BN, BSZ/BM), 256>>>(x, linear_w, linear_b, h, BSZ, FLATD, 36);

    for (int i = 0; i < NLAYER; i++) {
        const float* wq = Wq + (size_t)i * DM * DM;
        const float* wk = Wk + (size_t)i * DM * DM;
        const float* wv = Wv + (size_t)i * DM * DM;
        const float* wo = Wo + (size_t)i * DM * DM;
        const float* c1 = conv1_w + (size_t)i * DM * DFFN;
        const float* c2 = conv2_w + (size_t)i * DFFN * DM;

        sgemm_kernel<0,1><<<dim3(1, BL/BM), 256>>>(h, wq, bq + i*DM, q, BL, DM, DM);
        sgemm_kernel<0,1><<<dim3(1, BL/BM), 256>>>(h, wk, bk + i*DM, k, BL, DM, DM);
        sgemm_kernel<0,1><<<dim3(1, BL/BM), 256>>>(h, wv, bv + i*DM, v, BL, DM, DM);

        autocorr_kernel<<<BSZ, 128>>>(q, k, v, s);

        sgemm_kernel<0,1><<<dim3(1, BL/BM), 256>>>(s, wo, bo + i*DM, q, BL, DM, DM);
        decomp_add_kernel<<<BSZ, 128>>>(h, q, h);

        sgemm_kernel<1,0><<<dim3(DFFN/BN, BL/BM), 256>>>(h, c1, nullptr, t512, BL, DFFN, DM);
        sgemm_kernel<0,0><<<dim3(1, BL/BM), 256>>>(t512, c2, nullptr, s, BL, DM, DFFN);
        decomp_add_kernel<<<BSZ, 128>>>(h, s, h);
    }

    ln_kernel<<<BSZ, 128>>>(h, ln_w, ln_b, h);

    // ----- head: 3xTF32 tensor cores (fp32-accurate) -----
    tgemm3_kernel<1,1><<<dim3(FC1N/128, BSZ/128), 256>>>(h, fc1_w, fc1_b, z1, BSZ, FC1N, FLATD);
    tgemm3_kernel<0,1><<<dim3(FLATD/128, BSZ/128), 256>>>(z1, fc2_w, fc2_b, t512, BSZ, FLATD, FC1N);
    fc3_softmax_kernel<<<BSZ, 256>>>(t512, fc3_w, fc3_b, (float*)d_out);
}